// round 1
// baseline (speedup 1.0000x reference)
#include <cuda_runtime.h>
#include <cuda_bf16.h>
#include <math.h>

#define NN 4096
#define EE 16384
#define PHID 64
#define EPSF 1e-8f

// Scratch: B = A * diag(f_mean) in bf16 (32MB, L2-resident), per-node norms, f_mean.
__device__ __nv_bfloat16 g_B[(size_t)NN * NN];
__device__ float g_fmean[NN];
__device__ float g_d[NN];

__global__ void k_fmean(const float* __restrict__ f0, const float* __restrict__ f1) {
    int i = blockIdx.x * blockDim.x + threadIdx.x;
    if (i < NN) g_fmean[i] = 0.5f * (f0[i] + f1[i]);
}

// One CTA per row: scale row by f_mean, write bf16 B, compute fp32 norm of (m+eps).
__global__ __launch_bounds__(256) void k_prep(const float* __restrict__ A) {
    int row = blockIdx.x;
    const float4* a4 = (const float4*)(A + (size_t)row * NN);
    const float4* f4 = (const float4*)g_fmean;
    uint2* b4 = (uint2*)(g_B + (size_t)row * NN);
    float acc = 0.f;
#pragma unroll
    for (int it = 0; it < (NN / 4) / 256; ++it) {
        int q = threadIdx.x + it * 256;
        float4 v = a4[q];
        float4 f = f4[q];
        float m0 = v.x * f.x, m1 = v.y * f.y, m2 = v.z * f.z, m3 = v.w * f.w;
        float e0 = m0 + EPSF, e1 = m1 + EPSF, e2 = m2 + EPSF, e3 = m3 + EPSF;
        acc += e0 * e0 + e1 * e1;
        acc += e2 * e2 + e3 * e3;
        __nv_bfloat162 p0 = __floats2bfloat162_rn(m0, m1);
        __nv_bfloat162 p1 = __floats2bfloat162_rn(m2, m3);
        uint2 o;
        o.x = *(unsigned*)&p0;
        o.y = *(unsigned*)&p1;
        b4[q] = o;
    }
    __shared__ float sm[8];
#pragma unroll
    for (int off = 16; off; off >>= 1) acc += __shfl_xor_sync(0xffffffffu, acc, off);
    int wid = threadIdx.x >> 5, lane = threadIdx.x & 31;
    if (lane == 0) sm[wid] = acc;
    __syncthreads();
    if (threadIdx.x == 0) {
        float t = 0.f;
#pragma unroll
        for (int w = 0; w < 8; w++) t += sm[w];
        g_d[row] = sqrtf(t);
    }
}

__device__ __forceinline__ float b2lo(unsigned u) { return __uint_as_float(u << 16); }
__device__ __forceinline__ float b2hi(unsigned u) { return __uint_as_float(u & 0xffff0000u); }

// One warp per edge: bf16 row dot (L2-resident), normalize, then two 1->64->1 MLPs
// distributed across lanes (2 hidden units per lane + butterfly reduce).
__global__ __launch_bounds__(256) void k_edge(
    const int* __restrict__ src0, const int* __restrict__ dst0,
    const int* __restrict__ src1, const int* __restrict__ dst1,
    const float* __restrict__ p1w1, const float* __restrict__ p1b1,
    const float* __restrict__ p1w2, const float* __restrict__ p1b2,
    const float* __restrict__ p2w1, const float* __restrict__ p2b1,
    const float* __restrict__ p2w2, const float* __restrict__ p2b2,
    float* __restrict__ out) {
    int gw = (int)((blockIdx.x * blockDim.x + threadIdx.x) >> 5);
    int lane = threadIdx.x & 31;
    int layer = gw >> 14;  // gw / EE
    int e = gw & (EE - 1);
    int s = layer ? __ldg(src1 + e) : __ldg(src0 + e);
    int t = layer ? __ldg(dst1 + e) : __ldg(dst0 + e);

    const uint4* ps = (const uint4*)(g_B + (size_t)s * NN) + lane;
    const uint4* pt = (const uint4*)(g_B + (size_t)t * NN) + lane;

    float a0 = 0.f, a1 = 0.f, a2 = 0.f, a3 = 0.f;
#pragma unroll
    for (int k = 0; k < 16; k++) {
        uint4 a = ps[k * 32];
        uint4 b = pt[k * 32];
        a0 = fmaf(b2lo(a.x), b2lo(b.x), a0);
        a0 = fmaf(b2hi(a.x), b2hi(b.x), a0);
        a1 = fmaf(b2lo(a.y), b2lo(b.y), a1);
        a1 = fmaf(b2hi(a.y), b2hi(b.y), a1);
        a2 = fmaf(b2lo(a.z), b2lo(b.z), a2);
        a2 = fmaf(b2hi(a.z), b2hi(b.z), a2);
        a3 = fmaf(b2lo(a.w), b2lo(b.w), a3);
        a3 = fmaf(b2hi(a.w), b2hi(b.w), a3);
    }
    float acc = (a0 + a1) + (a2 + a3);
#pragma unroll
    for (int off = 16; off; off >>= 1) acc += __shfl_xor_sync(0xffffffffu, acc, off);

    float x = acc / (g_d[s] * g_d[t]);

    int o = layer * PHID;
    // MLP 1: 1 -> 64 -> 1
    float h0 = fmaxf(fmaf(x, p1w1[o + lane], p1b1[o + lane]), 0.f);
    float h1 = fmaxf(fmaf(x, p1w1[o + lane + 32], p1b1[o + lane + 32]), 0.f);
    float y = fmaf(h0, p1w2[o + lane], h1 * p1w2[o + lane + 32]);
#pragma unroll
    for (int off = 16; off; off >>= 1) y += __shfl_xor_sync(0xffffffffu, y, off);
    y += p1b2[layer];
    float x2 = 0.5f * y;  // BETA * y / LM

    // MLP 2: 1 -> 64 -> 1
    float g0 = fmaxf(fmaf(x2, p2w1[o + lane], p2b1[o + lane]), 0.f);
    float g1 = fmaxf(fmaf(x2, p2w1[o + lane + 32], p2b1[o + lane + 32]), 0.f);
    float z = fmaf(g0, p2w2[o + lane], g1 * p2w2[o + lane + 32]);
#pragma unroll
    for (int off = 16; off; off >>= 1) z += __shfl_xor_sync(0xffffffffu, z, off);
    z += p2b2[layer];

    if (lane == 0) out[gw] = z;
}

extern "C" void kernel_launch(void* const* d_in, const int* in_sizes, int n_in,
                              void* d_out, int out_size) {
    const float* A    = (const float*)d_in[0];
    const int* src0   = (const int*)d_in[1];
    const int* dst0   = (const int*)d_in[2];
    const int* src1   = (const int*)d_in[3];
    const int* dst1   = (const int*)d_in[4];
    const float* f0   = (const float*)d_in[5];
    const float* f1   = (const float*)d_in[6];
    const float* p1w1 = (const float*)d_in[7];
    const float* p1b1 = (const float*)d_in[8];
    const float* p1w2 = (const float*)d_in[9];
    const float* p1b2 = (const float*)d_in[10];
    const float* p2w1 = (const float*)d_in[11];
    const float* p2b1 = (const float*)d_in[12];
    const float* p2w2 = (const float*)d_in[13];
    const float* p2b2 = (const float*)d_in[14];
    float* out = (float*)d_out;

    k_fmean<<<(NN + 255) / 256, 256>>>(f0, f1);
    k_prep<<<NN, 256>>>(A);
    // 2*EE warps, 8 warps per CTA
    k_edge<<<(2 * EE) / 8, 256>>>(src0, dst0, src1, dst1,
                                  p1w1, p1b1, p1w2, p1b2,
                                  p2w1, p2b1, p2w2, p2b2, out);
}